// round 5
// baseline (speedup 1.0000x reference)
#include <cuda_runtime.h>

// Pooling_83141976916902: out[g, c] = sum_{i : batch[i]==g} x[i, c]
// (softmax over a size-1 axis == 1.0, so W/b are dead inputs)
//
// x:     [N, 128] float32   (d_in[0])
// batch: [N]      int64/int32, SORTED, values in [0, G)  (d_in[1])
// out:   [G, 128] float32
//
// Single kernel: one 128-thread block per segment. Two lanes binary-search
// the sorted batch array for this segment's [start, end) row range (batch is
// only 8MB -> L2-resident after the first wave), then 4 warps stream the
// rows (lane = float4 of 4 channels, 512B coalesced evict-first loads),
// smem cross-warp reduce, one plain 512B store. No atomics, no zero pass,
// no boundary pass.

#define C 128

__global__ __launch_bounds__(128)
void segsum_bs_kernel(const float4* __restrict__ x4,
                      const int* __restrict__ bw,   // batch as 32-bit words
                      float4* __restrict__ out,
                      int n, int G) {
    __shared__ int sbounds[2];
    const int g = blockIdx.x;
    const int warp = threadIdx.x >> 5;
    const int lane = threadIdx.x & 31;

    // Lanes 0 and 1 of warp 0: lower_bound(g) and lower_bound(g+1).
    if (threadIdx.x < 2) {
        // dtype probe: highest ODD 32-bit word. int64 high-half -> 0;
        // int32 payload is a sorted id near the end (~G-1) -> nonzero.
        int pidx = ((n - 1) & 1) ? (n - 1) : (n - 2);
        if (pidx < 0) pidx = 0;
        const int stride = (__ldg(&bw[pidx]) == 0) ? 2 : 1;  // words/elem

        const int target = g + threadIdx.x;
        int lo = 0, hi = n;
        while (lo < hi) {
            const int mid = (lo + hi) >> 1;
            const int v = __ldg(&bw[(size_t)mid * stride]);
            if (v < target) lo = mid + 1; else hi = mid;
        }
        sbounds[threadIdx.x] = lo;
    }
    __syncthreads();
    const int start = sbounds[0];
    const int end = sbounds[1];

    float4 acc = make_float4(0.f, 0.f, 0.f, 0.f);

    // Warp w owns rows start+w, start+w+4, ... ; 2-deep front-batched stream.
    int r = start + warp;
    for (; r + 4 < end; r += 8) {
        const float4 v0 = __ldcs(&x4[(size_t)r * (C / 4) + lane]);
        const float4 v1 = __ldcs(&x4[(size_t)(r + 4) * (C / 4) + lane]);
        acc.x += v0.x + v1.x;
        acc.y += v0.y + v1.y;
        acc.z += v0.z + v1.z;
        acc.w += v0.w + v1.w;
    }
    if (r < end) {
        const float4 v = __ldcs(&x4[(size_t)r * (C / 4) + lane]);
        acc.x += v.x;
        acc.y += v.y;
        acc.z += v.z;
        acc.w += v.w;
    }

    __shared__ float4 red[4][32];
    red[warp][lane] = acc;
    __syncthreads();

    if (warp == 0) {
        float4 a = red[0][lane];
        const float4 b = red[1][lane];
        const float4 c = red[2][lane];
        const float4 d = red[3][lane];
        a.x += b.x + c.x + d.x;
        a.y += b.y + c.y + d.y;
        a.z += b.z + c.z + d.z;
        a.w += b.w + c.w + d.w;
        out[(size_t)g * (C / 4) + lane] = a;  // empty segment -> zeros
    }
}

extern "C" void kernel_launch(void* const* d_in, const int* in_sizes, int n_in,
                              void* d_out, int out_size) {
    const float* x = (const float*)d_in[0];
    const int* batch_words = (const int*)d_in[1];
    (void)n_in;

    const int n_rows = in_sizes[1];   // N
    const int G = out_size / C;       // number of segments

    segsum_bs_kernel<<<G, 128>>>((const float4*)x, batch_words,
                                 (float4*)d_out, n_rows, G);
}

// round 6
// speedup vs baseline: 1.0248x; 1.0248x over previous
#include <cuda_runtime.h>

// Pooling_83141976916902: out[g, c] = sum_{i : batch[i]==g} x[i, c]
// (softmax over a size-1 axis == 1.0, so W/b are dead inputs)
//
// x:     [N, 128] float32   (d_in[0])
// batch: [N]      int64/int32, SORTED, values in [0, G)  (d_in[1])
// out:   [G, 128] float32
//
// Pass 1: zero the poisoned output (+ batch dtype probe).
// Pass 2: one warp owns 64 contiguous rows (two 32-row halves). Lane l holds
//         channels [4l,4l+4) as a float4 register accumulator; segment ids
//         live in registers (one per lane per half) and broadcast via shfl;
//         x rows stream as 8-deep front-batched evict-first LDG.128.
//         Flush via atomicAdd (REDG) only on segment change -> ~25.6K
//         512B flushes total (13MB L2 RMW).

#define C 128
#define WARPS_PER_BLOCK 8
#define ROWS_PER_WARP 64
#define ROWS_PER_BLOCK (WARPS_PER_BLOCK * ROWS_PER_WARP)  // 512

__device__ int g_batch_is_64;

__global__ void zero_and_detect_kernel(float4* __restrict__ out, int n_out4,
                                       const int* __restrict__ batch_words,
                                       int n_batch) {
    int i = blockIdx.x * blockDim.x + threadIdx.x;
    if (i < n_out4) out[i] = make_float4(0.f, 0.f, 0.f, 0.f);
    if (i == 0) {
        // highest ODD 32-bit word: int64 high-half -> 0; int32 payload -> ~G-1
        int idx = ((n_batch - 1) & 1) ? (n_batch - 1) : (n_batch - 2);
        if (idx < 0) idx = 0;
        g_batch_is_64 = (batch_words[idx] == 0) ? 1 : 0;
    }
}

__device__ __forceinline__ void flush_acc(float* __restrict__ out, int seg,
                                          int lane, float4& acc) {
    float* o = out + (size_t)seg * C + lane * 4;
    atomicAdd(o + 0, acc.x);
    atomicAdd(o + 1, acc.y);
    atomicAdd(o + 2, acc.z);
    atomicAdd(o + 3, acc.w);
    acc = make_float4(0.f, 0.f, 0.f, 0.f);
}

__global__ __launch_bounds__(256)
void segsum_kernel(const float4* __restrict__ x4,
                   const void* __restrict__ batch_raw,
                   float* __restrict__ out,
                   int n_rows) {
    const int warp = threadIdx.x >> 5;
    const int lane = threadIdx.x & 31;
    const int rstart = blockIdx.x * ROWS_PER_BLOCK + warp * ROWS_PER_WARP;
    if (rstart >= n_rows) return;

    const bool is64 = (g_batch_is_64 != 0);
    const long long* __restrict__ b64 = (const long long*)batch_raw;
    const int* __restrict__ b32 = (const int*)batch_raw;

    float4 acc = make_float4(0.f, 0.f, 0.f, 0.f);

    if (rstart + ROWS_PER_WARP <= n_rows) {
        // ---- fast path: full 64-row stripe, processed as two 32-row halves.
        int cur = is64 ? (int)b64[rstart] : b32[rstart];
        cur = __shfl_sync(0xFFFFFFFFu, cur, 0);

#pragma unroll
        for (int h = 0; h < 2; h++) {
            const int hstart = rstart + h * 32;
            // each lane loads the id of its own row (coalesced, once/half)
            const int r_lane = hstart + lane;
            const int my_id = is64 ? (int)b64[r_lane] : b32[r_lane];

            const float4* __restrict__ p = x4 + (size_t)hstart * (C / 4) + lane;

#pragma unroll
            for (int g = 0; g < 4; g++) {
                // front-batch 8 independent 16B streaming loads (MLP_p1 = 8)
                float4 v0 = __ldcs(p + (g * 8 + 0) * (C / 4));
                float4 v1 = __ldcs(p + (g * 8 + 1) * (C / 4));
                float4 v2 = __ldcs(p + (g * 8 + 2) * (C / 4));
                float4 v3 = __ldcs(p + (g * 8 + 3) * (C / 4));
                float4 v4 = __ldcs(p + (g * 8 + 4) * (C / 4));
                float4 v5 = __ldcs(p + (g * 8 + 5) * (C / 4));
                float4 v6 = __ldcs(p + (g * 8 + 6) * (C / 4));
                float4 v7 = __ldcs(p + (g * 8 + 7) * (C / 4));

                float4 vv[8] = {v0, v1, v2, v3, v4, v5, v6, v7};
#pragma unroll
                for (int j = 0; j < 8; j++) {
                    const int s = __shfl_sync(0xFFFFFFFFu, my_id, g * 8 + j);
                    if (s != cur) {
                        flush_acc(out, cur, lane, acc);
                        cur = s;
                    }
                    acc.x += vv[j].x;
                    acc.y += vv[j].y;
                    acc.z += vv[j].z;
                    acc.w += vv[j].w;
                }
            }
        }
        flush_acc(out, cur, lane, acc);
    } else {
        // ---- generic tail path ----
        const int rend = n_rows;
        int cur = is64 ? (int)b64[rstart] : b32[rstart];
        for (int r = rstart; r < rend; r++) {
            const int s = is64 ? (int)b64[r] : b32[r];
            const float4 v = __ldcs(x4 + (size_t)r * (C / 4) + lane);
            if (s != cur) {
                flush_acc(out, cur, lane, acc);
                cur = s;
            }
            acc.x += v.x;
            acc.y += v.y;
            acc.z += v.z;
            acc.w += v.w;
        }
        flush_acc(out, cur, lane, acc);
    }
}

extern "C" void kernel_launch(void* const* d_in, const int* in_sizes, int n_in,
                              void* d_out, int out_size) {
    const float* x = (const float*)d_in[0];
    const void* batch = d_in[1];
    (void)n_in;

    const int n_rows = in_sizes[1];
    const int n_out4 = out_size / 4;

    {
        int threads = 256;
        int blocks = (n_out4 + threads - 1) / threads;
        if (blocks < 1) blocks = 1;
        zero_and_detect_kernel<<<blocks, threads>>>(
            (float4*)d_out, n_out4, (const int*)batch, n_rows);
    }
    {
        int blocks = (n_rows + ROWS_PER_BLOCK - 1) / ROWS_PER_BLOCK;
        segsum_kernel<<<blocks, 256>>>(
            (const float4*)x, batch, (float*)d_out, n_rows);
    }
}

// round 7
// speedup vs baseline: 1.1246x; 1.0974x over previous
#include <cuda_runtime.h>

// Pooling_83141976916902: out[g, c] = sum_{i : batch[i]==g} x[i, c]
// (softmax over a size-1 axis == 1.0, so W/b are dead inputs)
//
// x:     [N, 128] float32   (d_in[0])
// batch: [N]      int64/int32, SORTED, values in [0, G)  (d_in[1])
// out:   [G, 128] float32
//
// R3 structure (proven fastest): 32 rows/warp, ids hoisted to registers,
// 8-deep front-batched evict-first LDG.128 stream, atomic flush on segment
// change. R7 change: flush uses ONE red.global.add.v4.f32 (REDG.128) per
// lane instead of four scalar ATOMG.F32 -> 4x fewer L2 atomic ops.

#define C 128
#define WARPS_PER_BLOCK 8
#define ROWS_PER_WARP 32
#define ROWS_PER_BLOCK (WARPS_PER_BLOCK * ROWS_PER_WARP)  // 256

__device__ int g_batch_is_64;

// Pass 1: zero the (0xAA-poisoned) output and detect batch dtype.
// Highest ODD 32-bit word: int64 high-half -> 0; int32 payload (~G-1) -> nonzero.
__global__ void zero_and_detect_kernel(float4* __restrict__ out, int n_out4,
                                       const int* __restrict__ batch_words,
                                       int n_batch) {
    int i = blockIdx.x * blockDim.x + threadIdx.x;
    if (i < n_out4) out[i] = make_float4(0.f, 0.f, 0.f, 0.f);
    if (i == 0) {
        int idx = ((n_batch - 1) & 1) ? (n_batch - 1) : (n_batch - 2);
        if (idx < 0) idx = 0;
        g_batch_is_64 = (batch_words[idx] == 0) ? 1 : 0;
    }
}

// One vector reduction (REDG.128, no return) per lane. 16B-aligned by
// construction: out + seg*512B + lane*16B.
__device__ __forceinline__ void flush_acc(float* __restrict__ out, int seg,
                                          int lane, float4& acc) {
    float* o = out + (size_t)seg * C + lane * 4;
    asm volatile("red.global.add.v4.f32 [%0], {%1, %2, %3, %4};"
                 :: "l"(o), "f"(acc.x), "f"(acc.y), "f"(acc.z), "f"(acc.w)
                 : "memory");
    acc = make_float4(0.f, 0.f, 0.f, 0.f);
}

// Pass 2: segmented sum. One warp owns 32 contiguous rows. Lane l holds
// channels [4l,4l+4) as a float4 accumulator (one coalesced 512B row read).
// Segment ids are loaded ONCE per stripe into registers (one per lane) and
// broadcast per-row via shfl; x rows are loaded in front-batched groups of 8
// independent LDG.128 (streaming, evict-first) before any flush logic.
__global__ __launch_bounds__(ROWS_PER_BLOCK)
void segsum_kernel(const float4* __restrict__ x4,
                   const void* __restrict__ batch_raw,
                   float* __restrict__ out,
                   int n_rows) {
    const int warp = threadIdx.x >> 5;
    const int lane = threadIdx.x & 31;
    const int rstart = blockIdx.x * ROWS_PER_BLOCK + warp * ROWS_PER_WARP;
    if (rstart >= n_rows) return;

    const bool is64 = (g_batch_is_64 != 0);
    const long long* __restrict__ b64 = (const long long*)batch_raw;
    const int* __restrict__ b32 = (const int*)batch_raw;

    float4 acc = make_float4(0.f, 0.f, 0.f, 0.f);

    if (rstart + ROWS_PER_WARP <= n_rows) {
        // ---- fast path: full 32-row stripe (always taken when N % 32 == 0) ----
        const int r_lane = rstart + lane;
        int my_id = is64 ? (int)b64[r_lane] : b32[r_lane];

        const float4* __restrict__ p = x4 + (size_t)rstart * (C / 4) + lane;
        int cur = __shfl_sync(0xFFFFFFFFu, my_id, 0);

#pragma unroll
        for (int g = 0; g < ROWS_PER_WARP / 8; g++) {
            // front-batch 8 independent 16B streaming loads (MLP_p1 = 8)
            float4 v0 = __ldcs(p + (g * 8 + 0) * (C / 4));
            float4 v1 = __ldcs(p + (g * 8 + 1) * (C / 4));
            float4 v2 = __ldcs(p + (g * 8 + 2) * (C / 4));
            float4 v3 = __ldcs(p + (g * 8 + 3) * (C / 4));
            float4 v4 = __ldcs(p + (g * 8 + 4) * (C / 4));
            float4 v5 = __ldcs(p + (g * 8 + 5) * (C / 4));
            float4 v6 = __ldcs(p + (g * 8 + 6) * (C / 4));
            float4 v7 = __ldcs(p + (g * 8 + 7) * (C / 4));

            float4 vv[8] = {v0, v1, v2, v3, v4, v5, v6, v7};
#pragma unroll
            for (int j = 0; j < 8; j++) {
                const int s = __shfl_sync(0xFFFFFFFFu, my_id, g * 8 + j);
                if (s != cur) {
                    flush_acc(out, cur, lane, acc);
                    cur = s;
                }
                acc.x += vv[j].x;
                acc.y += vv[j].y;
                acc.z += vv[j].z;
                acc.w += vv[j].w;
            }
        }
        flush_acc(out, cur, lane, acc);
    } else {
        // ---- generic tail path ----
        const int rend = n_rows;
        int cur = is64 ? (int)b64[rstart] : b32[rstart];
        for (int r = rstart; r < rend; r++) {
            const int s = is64 ? (int)b64[r] : b32[r];
            const float4 v = __ldcs(x4 + (size_t)r * (C / 4) + lane);
            if (s != cur) {
                flush_acc(out, cur, lane, acc);
                cur = s;
            }
            acc.x += v.x;
            acc.y += v.y;
            acc.z += v.z;
            acc.w += v.w;
        }
        flush_acc(out, cur, lane, acc);
    }
}

extern "C" void kernel_launch(void* const* d_in, const int* in_sizes, int n_in,
                              void* d_out, int out_size) {
    const float* x = (const float*)d_in[0];
    const void* batch = d_in[1];
    (void)n_in;

    const int n_rows = in_sizes[1];
    const int n_out4 = out_size / 4;

    {
        int threads = 256;
        int blocks = (n_out4 + threads - 1) / threads;
        if (blocks < 1) blocks = 1;
        zero_and_detect_kernel<<<blocks, threads>>>(
            (float4*)d_out, n_out4, (const int*)batch, n_rows);
    }
    {
        int blocks = (n_rows + ROWS_PER_BLOCK - 1) / ROWS_PER_BLOCK;
        segsum_kernel<<<blocks, ROWS_PER_BLOCK>>>(
            (const float4*)x, batch, (float*)d_out, n_rows);
    }
}

// round 9
// speedup vs baseline: 1.1284x; 1.0034x over previous
#include <cuda_runtime.h>

// Pooling_83141976916902: out[g, c] = sum_{i : batch[i]==g} x[i, c]
// (softmax over a size-1 axis == 1.0, so W/b are dead inputs)
//
// x:     [N, 128] float32   (d_in[0])
// batch: [N]      int64/int32, SORTED, values in [0, G)  (d_in[1])
// out:   [G, 128] float32
//
// R7 structure (at HBM ceiling: 525MB compulsory / 6.8TB/s):
//   32 rows/warp, ids hoisted to registers, 8-deep front-batched
//   evict-first LDG.128 stream, red.global.add.v4.f32 flush on segment
//   change.
// R8 changes: zeroing via graph memset node (cudaMemsetAsync) instead of a
//   kernel; dtype probe moved in-kernel (one L2-hit broadcast load/block).

#define C 128
#define WARPS_PER_BLOCK 8
#define ROWS_PER_WARP 32
#define ROWS_PER_BLOCK (WARPS_PER_BLOCK * ROWS_PER_WARP)  // 256

// One vector reduction (REDG.128, no return) per lane. 16B-aligned by
// construction: out + seg*512B + lane*16B.
__device__ __forceinline__ void flush_acc(float* __restrict__ out, int seg,
                                          int lane, float4& acc) {
    float* o = out + (size_t)seg * C + lane * 4;
    asm volatile("red.global.add.v4.f32 [%0], {%1, %2, %3, %4};"
                 :: "l"(o), "f"(acc.x), "f"(acc.y), "f"(acc.z), "f"(acc.w)
                 : "memory");
    acc = make_float4(0.f, 0.f, 0.f, 0.f);
}

// Segmented sum. One warp owns 32 contiguous rows. Lane l holds channels
// [4l,4l+4) as a float4 accumulator (one coalesced 512B row read). Segment
// ids are loaded ONCE per stripe into registers (one per lane) and broadcast
// per-row via shfl; x rows are loaded in front-batched groups of 8
// independent LDG.128 (streaming, evict-first) before any flush logic.
__global__ __launch_bounds__(ROWS_PER_BLOCK)
void segsum_kernel(const float4* __restrict__ x4,
                   const void* __restrict__ batch_raw,
                   float* __restrict__ out,
                   int n_rows) {
    const int warp = threadIdx.x >> 5;
    const int lane = threadIdx.x & 31;
    const int rstart = blockIdx.x * ROWS_PER_BLOCK + warp * ROWS_PER_WARP;
    if (rstart >= n_rows) return;

    // In-kernel dtype probe: highest ODD 32-bit word of the batch buffer.
    // int64 (values < 2^31): odd words are high halves -> 0.
    // int32: that word is a sorted id near the end (~G-1) -> nonzero.
    // Broadcast L2/L1-hit load: effectively free per block.
    const int* __restrict__ bwords = (const int*)batch_raw;
    int pidx = ((n_rows - 1) & 1) ? (n_rows - 1) : (n_rows - 2);
    if (pidx < 0) pidx = 0;
    const bool is64 = (__ldg(&bwords[pidx]) == 0);

    const long long* __restrict__ b64 = (const long long*)batch_raw;
    const int* __restrict__ b32 = (const int*)batch_raw;

    float4 acc = make_float4(0.f, 0.f, 0.f, 0.f);

    if (rstart + ROWS_PER_WARP <= n_rows) {
        // ---- fast path: full 32-row stripe (always taken when N % 32 == 0) ----
        const int r_lane = rstart + lane;
        int my_id = is64 ? (int)b64[r_lane] : b32[r_lane];

        const float4* __restrict__ p = x4 + (size_t)rstart * (C / 4) + lane;
        int cur = __shfl_sync(0xFFFFFFFFu, my_id, 0);

#pragma unroll
        for (int g = 0; g < ROWS_PER_WARP / 8; g++) {
            // front-batch 8 independent 16B streaming loads (MLP_p1 = 8)
            float4 v0 = __ldcs(p + (g * 8 + 0) * (C / 4));
            float4 v1 = __ldcs(p + (g * 8 + 1) * (C / 4));
            float4 v2 = __ldcs(p + (g * 8 + 2) * (C / 4));
            float4 v3 = __ldcs(p + (g * 8 + 3) * (C / 4));
            float4 v4 = __ldcs(p + (g * 8 + 4) * (C / 4));
            float4 v5 = __ldcs(p + (g * 8 + 5) * (C / 4));
            float4 v6 = __ldcs(p + (g * 8 + 6) * (C / 4));
            float4 v7 = __ldcs(p + (g * 8 + 7) * (C / 4));

            float4 vv[8] = {v0, v1, v2, v3, v4, v5, v6, v7};
#pragma unroll
            for (int j = 0; j < 8; j++) {
                const int s = __shfl_sync(0xFFFFFFFFu, my_id, g * 8 + j);
                if (s != cur) {
                    flush_acc(out, cur, lane, acc);
                    cur = s;
                }
                acc.x += vv[j].x;
                acc.y += vv[j].y;
                acc.z += vv[j].z;
                acc.w += vv[j].w;
            }
        }
        flush_acc(out, cur, lane, acc);
    } else {
        // ---- generic tail path ----
        const int rend = n_rows;
        int cur = is64 ? (int)b64[rstart] : b32[rstart];
        for (int r = rstart; r < rend; r++) {
            const int s = is64 ? (int)b64[r] : b32[r];
            const float4 v = __ldcs(x4 + (size_t)r * (C / 4) + lane);
            if (s != cur) {
                flush_acc(out, cur, lane, acc);
                cur = s;
            }
            acc.x += v.x;
            acc.y += v.y;
            acc.z += v.z;
            acc.w += v.w;
        }
        flush_acc(out, cur, lane, acc);
    }
}

extern "C" void kernel_launch(void* const* d_in, const int* in_sizes, int n_in,
                              void* d_out, int out_size) {
    const float* x = (const float*)d_in[0];
    const void* batch = d_in[1];
    (void)n_in;

    const int n_rows = in_sizes[1];

    // Zero the poisoned output: graph-capturable memset node (no alloc,
    // no sync). out_size floats.
    cudaMemsetAsync(d_out, 0, (size_t)out_size * sizeof(float), 0);

    int blocks = (n_rows + ROWS_PER_BLOCK - 1) / ROWS_PER_BLOCK;
    segsum_kernel<<<blocks, ROWS_PER_BLOCK>>>(
        (const float4*)x, batch, (float*)d_out, n_rows);
}